// round 16
// baseline (speedup 1.0000x reference)
#include <cuda_runtime.h>
#include <cuda_bf16.h>
#include <cstdint>

// Problem constants
#define BB     8
#define NN     2048
#define DF     256     // d_feat
#define KF     257     // d_feat + 1
#define DH     64      // head dim
#define QKW    128     // q(64) | k(64) packed per row

// ---------------- scratch (__device__ globals; no allocation) ----------------
__device__ float g_QK[(size_t)BB * NN * QKW];          // [row][0..63]=q, [64..127]=k
__device__ float g_cs_part[(size_t)BB * 16 * NN];      // per-(b, n-tile) column-sum partials
__device__ float g_cs[(size_t)BB * NN];                // final column sums
__device__ float g_y_part[(size_t)BB * 16 * NN * 3];   // per-(b, n-chunk) y partials

// ---------------- mma helpers ----------------
__device__ __forceinline__ uint32_t smem_u32(const void* p) {
    uint32_t a;
    asm("{ .reg .u64 t; cvta.to.shared.u64 t, %1; cvt.u32.u64 %0, t; }"
        : "=r"(a) : "l"(p));
    return a;
}
__device__ __forceinline__ void ldsm_x4(uint32_t& r0, uint32_t& r1,
                                        uint32_t& r2, uint32_t& r3, uint32_t addr) {
    asm volatile("ldmatrix.sync.aligned.m8n8.x4.shared.b16 {%0,%1,%2,%3}, [%4];"
                 : "=r"(r0), "=r"(r1), "=r"(r2), "=r"(r3) : "r"(addr));
}
__device__ __forceinline__ void mma_bf16(float& c0, float& c1, float& c2, float& c3,
                                         uint32_t a0, uint32_t a1, uint32_t a2, uint32_t a3,
                                         uint32_t b0, uint32_t b1) {
    asm volatile(
        "mma.sync.aligned.m16n8k16.row.col.f32.bf16.bf16.f32 "
        "{%0,%1,%2,%3}, {%4,%5,%6,%7}, {%8,%9}, {%0,%1,%2,%3};"
        : "+f"(c0), "+f"(c1), "+f"(c2), "+f"(c3)
        : "r"(a0), "r"(a1), "r"(a2), "r"(a3), "r"(b0), "r"(b1));
}
__device__ __forceinline__ uint32_t pack_bf2(__nv_bfloat16 lo, __nv_bfloat16 hi) {
    __nv_bfloat162 v; v.x = lo; v.y = hi;
    return *(uint32_t*)&v;
}

// =============================================================================
// K1 (scalar, measured-good): fc = [f | log_eps] ; QK = fc @ [W_q | W_k]
// =============================================================================
__global__ __launch_bounds__(256) void k1_proj(
    const float* __restrict__ f, const float* __restrict__ le,
    const float* __restrict__ Wq, const float* __restrict__ Wk)
{
    __shared__ float As[32][68];
    __shared__ float Bs[32][132];

    const int t  = threadIdx.x;
    const int ty = t >> 4;
    const int tx = t & 15;
    const int rowBase = blockIdx.x * 64;
    const int b = rowBase / NN;

    float acc[4][8];
    #pragma unroll
    for (int i = 0; i < 4; i++)
        #pragma unroll
        for (int j = 0; j < 8; j++) acc[i][j] = 0.f;

    for (int kc = 0; kc < 9; kc++) {
        const int k0 = kc * 32;
        const int len = (KF - k0 < 32) ? (KF - k0) : 32;
        __syncthreads();
        if (len == 32) {
            #pragma unroll
            for (int it = 0; it < 2; it++) {
                int n  = (t >> 3) + it * 32;
                int kk = (t & 7) * 4;
                float4 v = *(const float4*)&f[(size_t)(rowBase + n) * DF + k0 + kk];
                As[kk + 0][n] = v.x; As[kk + 1][n] = v.y;
                As[kk + 2][n] = v.z; As[kk + 3][n] = v.w;
            }
            #pragma unroll
            for (int it = 0; it < 4; it++) {
                int kk = (t >> 5) + it * 8;
                int h  = (t & 31) * 4;
                int c  = k0 + kk;
                float4 v = (h < 64) ? *(const float4*)&Wq[c * DH + h]
                                    : *(const float4*)&Wk[c * DH + (h - 64)];
                Bs[kk][h + 0] = v.x; Bs[kk][h + 1] = v.y;
                Bs[kk][h + 2] = v.z; Bs[kk][h + 3] = v.w;
            }
        } else {
            float lv = le[b];
            for (int idx = t; idx < 32 * 64; idx += 256) {
                int kk = idx >> 6, n = idx & 63;
                As[kk][n] = (kk == 0) ? lv : 0.f;
            }
            if (t < 32) {
                int h = t * 4;
                float4 v = (h < 64) ? *(const float4*)&Wq[256 * DH + h]
                                    : *(const float4*)&Wk[256 * DH + (h - 64)];
                Bs[0][h + 0] = v.x; Bs[0][h + 1] = v.y;
                Bs[0][h + 2] = v.z; Bs[0][h + 3] = v.w;
            }
        }
        __syncthreads();
        #pragma unroll 8
        for (int kk = 0; kk < 32; kk++) {
            float4 av = *(const float4*)&As[kk][ty * 4];
            float4 b0 = *(const float4*)&Bs[kk][tx * 8];
            float4 b1 = *(const float4*)&Bs[kk][tx * 8 + 4];
            float a[4]  = {av.x, av.y, av.z, av.w};
            float bv[8] = {b0.x, b0.y, b0.z, b0.w, b1.x, b1.y, b1.z, b1.w};
            #pragma unroll
            for (int i = 0; i < 4; i++)
                #pragma unroll
                for (int j = 0; j < 8; j++) acc[i][j] += a[i] * bv[j];
        }
    }
    #pragma unroll
    for (int i = 0; i < 4; i++) {
        int row = rowBase + ty * 4 + i;
        float4 o0 = {acc[i][0], acc[i][1], acc[i][2], acc[i][3]};
        float4 o1 = {acc[i][4], acc[i][5], acc[i][6], acc[i][7]};
        *(float4*)&g_QK[(size_t)row * QKW + tx * 8]     = o0;
        *(float4*)&g_QK[(size_t)row * QKW + tx * 8 + 4] = o1;
    }
}

// =============================================================================
// K2 (bf16 mma.sync, 3-term split): E = exp(q.k/8) -> pi + colsum partials.
// 128n x 128m tile, K=64, 256 threads (8 warps: 4n x 2m), warp 32n x 64m.
// Dyn smem bf16: A_hi|A_lo|B_hi|B_lo, each [128][72] (144B rows) = 73728 B.
// R16 change: allow 2 CTAs/SM (was forced 1) -> 16 warps/SM latency hiding.
// =============================================================================
#define K2_SMEM_BYTES 73728
#define RSTR 72            // bf16 elems per row (144 B)
#define AB_HI 0
#define AB_LO 18432
#define BB_HI 36864
#define BB_LO 55296
#define S_STR 136
#define CS2F  17408        // float offset of 256-float colsum scratch

__global__ __launch_bounds__(256, 2) void k2_tc(float* __restrict__ pi)
{
    extern __shared__ char sm[];
    float* smf = (float*)sm;
    const int t    = threadIdx.x;
    const int wid  = t >> 5;
    const int lane = t & 31;
    const int g    = lane >> 2;
    const int c4   = lane & 3;
    const int m0   = blockIdx.x * 128;
    const int n0   = blockIdx.y * 128;
    const int b    = blockIdx.z;
    const float* __restrict__ Q = g_QK + (size_t)b * NN * QKW;

    // ---- load + bf16 hi/lo split: thread t -> one row (Q for t<128, K else)
    {
        const int r = t & 127;
        const float* src = (t < 128) ? &Q[(size_t)(n0 + r) * QKW]
                                     : &Q[(size_t)(m0 + r) * QKW + 64];
        char* dhi = sm + ((t < 128) ? AB_HI : BB_HI) + r * 144;
        char* dlo = sm + ((t < 128) ? AB_LO : BB_LO) + r * 144;
        #pragma unroll
        for (int gg = 0; gg < 16; gg++) {
            float4 v = *(const float4*)&src[gg * 4];
            __nv_bfloat16 hx = __float2bfloat16(v.x);
            __nv_bfloat16 hy = __float2bfloat16(v.y);
            __nv_bfloat16 hz = __float2bfloat16(v.z);
            __nv_bfloat16 hw = __float2bfloat16(v.w);
            __nv_bfloat16 lx = __float2bfloat16(v.x - __bfloat162float(hx));
            __nv_bfloat16 ly = __float2bfloat16(v.y - __bfloat162float(hy));
            __nv_bfloat16 lz = __float2bfloat16(v.z - __bfloat162float(hz));
            __nv_bfloat16 lw = __float2bfloat16(v.w - __bfloat162float(hw));
            uint2 hp = make_uint2(pack_bf2(hx, hy), pack_bf2(hz, hw));
            uint2 lp = make_uint2(pack_bf2(lx, ly), pack_bf2(lz, lw));
            *(uint2*)(dhi + gg * 8) = hp;
            *(uint2*)(dlo + gg * 8) = lp;
        }
    }
    __syncthreads();

    // ---- mainloop: 3 passes (hi*hi, lo*hi, hi*lo) x 4 k-steps x 16 mma ----
    const int warpN = wid >> 1;
    const int warpM = wid & 1;
    const int nbase = warpN * 32;
    const int mbase = warpM * 64;
    const int lane15 = lane & 15;
    const int kby    = (lane >> 4) * 16;   // byte offset of k-half (8 bf16)

    float acc[2][8][4];
    #pragma unroll
    for (int mi = 0; mi < 2; mi++)
        #pragma unroll
        for (int nj = 0; nj < 8; nj++)
            #pragma unroll
            for (int c = 0; c < 4; c++) acc[mi][nj][c] = 0.f;

    #pragma unroll
    for (int p = 0; p < 3; p++) {
        const char* Ab = sm + ((p == 1) ? AB_LO : AB_HI);
        const char* Bb = sm + ((p == 2) ? BB_LO : BB_HI);
        const uint32_t aBase = smem_u32(Ab + (nbase + lane15) * 144 + kby);
        const uint32_t bBase = smem_u32(Bb + (mbase + lane15) * 144 + kby);
        #pragma unroll
        for (int ks = 0; ks < 4; ks++) {
            const uint32_t ko = ks * 32;   // 16 bf16 = 32 bytes per k-step
            uint32_t a0[4], a1[4];
            ldsm_x4(a0[0], a0[1], a0[2], a0[3], aBase + ko);
            ldsm_x4(a1[0], a1[1], a1[2], a1[3], aBase + 16 * 144 + ko);
            #pragma unroll
            for (int jb = 0; jb < 4; jb++) {
                uint32_t r0, r1, r2, r3;
                ldsm_x4(r0, r1, r2, r3, bBase + jb * 16 * 144 + ko);
                // r0/r2 -> m-tile 2jb (b0,b1); r1/r3 -> m-tile 2jb+1
                mma_bf16(acc[0][2*jb][0], acc[0][2*jb][1], acc[0][2*jb][2], acc[0][2*jb][3],
                         a0[0], a0[1], a0[2], a0[3], r0, r2);
                mma_bf16(acc[0][2*jb+1][0], acc[0][2*jb+1][1], acc[0][2*jb+1][2], acc[0][2*jb+1][3],
                         a0[0], a0[1], a0[2], a0[3], r1, r3);
                mma_bf16(acc[1][2*jb][0], acc[1][2*jb][1], acc[1][2*jb][2], acc[1][2*jb][3],
                         a1[0], a1[1], a1[2], a1[3], r0, r2);
                mma_bf16(acc[1][2*jb+1][0], acc[1][2*jb+1][1], acc[1][2*jb+1][2], acc[1][2*jb+1][3],
                         a1[0], a1[1], a1[2], a1[3], r1, r3);
            }
        }
    }
    __syncthreads();   // done reading A/B smem; S overlays it

    // ---- exp + stage into S[128][136] ----
    #pragma unroll
    for (int mi = 0; mi < 2; mi++) {
        const int nr0 = nbase + mi * 16 + g;
        #pragma unroll
        for (int nj = 0; nj < 8; nj++) {
            const int mc = mbase + nj * 8 + 2 * c4;
            float e0 = __expf(acc[mi][nj][0] * 0.125f);
            float e1 = __expf(acc[mi][nj][1] * 0.125f);
            float e2 = __expf(acc[mi][nj][2] * 0.125f);
            float e3 = __expf(acc[mi][nj][3] * 0.125f);
            *(float2*)&smf[nr0 * S_STR + mc]       = make_float2(e0, e1);
            *(float2*)&smf[(nr0 + 8) * S_STR + mc] = make_float2(e2, e3);
        }
    }
    __syncthreads();

    // ---- coalesced pi stores from S ----
    const size_t piBase = (size_t)b * NN * NN;
    #pragma unroll
    for (int i = 0; i < 16; i++) {
        int row = wid + i * 8;
        float4 v = *(const float4*)&smf[row * S_STR + lane * 4];
        *(float4*)&pi[piBase + (size_t)(n0 + row) * NN + m0 + lane * 4] = v;
    }

    // ---- deterministic column sums ----
    {
        const int col = t & 127, half = t >> 7;
        float s = 0.f;
        #pragma unroll 8
        for (int n = 0; n < 64; n++) s += smf[(half * 64 + n) * S_STR + col];
        smf[CS2F + half * 128 + col] = s;
    }
    __syncthreads();
    if (t < 128) {
        float s = smf[CS2F + t] + smf[CS2F + 128 + t];
        g_cs_part[(size_t)(b * 16 + blockIdx.y) * NN + m0 + t] = s;
    }
}

// K2b: colsum[b][m] = sum over 16 n-tiles
__global__ void k2b_reduce()
{
    int i = blockIdx.x * 256 + threadIdx.x;
    int b = i >> 11, m = i & (NN - 1);
    float s = 0.f;
    #pragma unroll
    for (int nt = 0; nt < 16; nt++) s += g_cs_part[(size_t)(b * 16 + nt) * NN + m];
    g_cs[i] = s;
}

// =============================================================================
// K3 (R10 measured-good): normalize pi in place + y partials
// =============================================================================
__global__ __launch_bounds__(256) void k3_norm(
    const float* __restrict__ x, float* __restrict__ pi)
{
    __shared__ float xs[128 * 3];
    const int t  = threadIdx.x;
    const int m  = blockIdx.x * 256 + t;
    const int nc = blockIdx.y;
    const int b  = blockIdx.z;
    const float* xb = x + (size_t)b * NN * 3 + (size_t)(nc * 128) * 3;
    for (int i = t; i < 128 * 3; i += 256) xs[i] = xb[i];
    const float inv  = 1.0f / g_cs[(size_t)b * NN + m];
    const float invN = 1.0f / (float)NN;
    __syncthreads();

    float a0 = 0.f, a1 = 0.f, a2 = 0.f;
    size_t base = (size_t)b * NN * NN + (size_t)(nc * 128) * NN + m;
    #pragma unroll 2
    for (int nb = 0; nb < 16; nb++) {
        float* pp = pi + base + (size_t)(nb * 8) * NN;
        float e[8];
        #pragma unroll
        for (int u = 0; u < 8; u++) e[u] = __ldcs(pp + (size_t)u * NN);
        #pragma unroll
        for (int u = 0; u < 8; u++) {
            float p = e[u] * inv;
            __stcs(pp + (size_t)u * NN, p * invN);
            int n = nb * 8 + u;
            a0 += p * xs[n * 3 + 0];
            a1 += p * xs[n * 3 + 1];
            a2 += p * xs[n * 3 + 2];
        }
    }
    size_t yi = ((size_t)(b * 16 + nc) * NN + m) * 3;
    g_y_part[yi + 0] = a0;
    g_y_part[yi + 1] = a1;
    g_y_part[yi + 2] = a2;
}

// K4: reduce y partials into d_out's y region
__global__ void k4_reduce(float* __restrict__ y)
{
    int i = blockIdx.x * 256 + threadIdx.x;
    int b = i / (NN * 3);
    int r = i - b * (NN * 3);
    float s = 0.f;
    #pragma unroll
    for (int nc = 0; nc < 16; nc++)
        s += g_y_part[(size_t)(b * 16 + nc) * (NN * 3) + r];
    y[i] = s;
}

// =============================================================================
extern "C" void kernel_launch(void* const* d_in, const int* in_sizes, int n_in,
                              void* d_out, int out_size)
{
    const float* f  = (const float*)d_in[0];   // (B, N, 256)
    const float* x  = (const float*)d_in[1];   // (B, N, 3)
    const float* le = (const float*)d_in[2];   // (B,)
    const float* Wq = (const float*)d_in[3];   // (257, 64)
    const float* Wk = (const float*)d_in[4];   // (257, 64)

    float* out = (float*)d_out;
    float* y   = out;                          // (B, N, 3)
    float* pi  = out + (size_t)BB * NN * 3;    // (B, N, N)

    static int smem_set = 0;
    if (!smem_set) {
        cudaFuncSetAttribute(k2_tc, cudaFuncAttributeMaxDynamicSharedMemorySize,
                             K2_SMEM_BYTES);
        smem_set = 1;
    }

    k1_proj<<<(BB * NN) / 64, 256>>>(f, le, Wq, Wk);
    k2_tc<<<dim3(16, 16, BB), 256, K2_SMEM_BYTES>>>(pi);
    k2b_reduce<<<(BB * NN) / 256, 256>>>();
    k3_norm<<<dim3(8, 16, BB), 256>>>(x, pi);
    k4_reduce<<<(BB * NN * 3) / 256, 256>>>(y);
}

// round 17
// speedup vs baseline: 1.4120x; 1.4120x over previous
#include <cuda_runtime.h>
#include <cuda_bf16.h>
#include <cstdint>

// Problem constants
#define BB     8
#define NN     2048
#define DF     256     // d_feat
#define KF     257     // d_feat + 1
#define DH     64      // head dim
#define QKW    128     // q(64) | k(64) packed per row

// ---------------- scratch (__device__ globals; no allocation) ----------------
__device__ float g_QK[(size_t)BB * NN * QKW];          // [row][0..63]=q, [64..127]=k
__device__ float g_cs_part[(size_t)BB * 16 * NN];      // per-(b, n-tile) column-sum partials
__device__ float g_cs[(size_t)BB * NN];                // final column sums
__device__ float g_y_part[(size_t)BB * 16 * NN * 3];   // per-(b, n-chunk) y partials

// ---------------- mma helpers ----------------
__device__ __forceinline__ uint32_t smem_u32(const void* p) {
    uint32_t a;
    asm("{ .reg .u64 t; cvta.to.shared.u64 t, %1; cvt.u32.u64 %0, t; }"
        : "=r"(a) : "l"(p));
    return a;
}
__device__ __forceinline__ void ldsm_x4(uint32_t& r0, uint32_t& r1,
                                        uint32_t& r2, uint32_t& r3, uint32_t addr) {
    asm volatile("ldmatrix.sync.aligned.m8n8.x4.shared.b16 {%0,%1,%2,%3}, [%4];"
                 : "=r"(r0), "=r"(r1), "=r"(r2), "=r"(r3) : "r"(addr));
}
__device__ __forceinline__ void mma_bf16(float& c0, float& c1, float& c2, float& c3,
                                         uint32_t a0, uint32_t a1, uint32_t a2, uint32_t a3,
                                         uint32_t b0, uint32_t b1) {
    asm volatile(
        "mma.sync.aligned.m16n8k16.row.col.f32.bf16.bf16.f32 "
        "{%0,%1,%2,%3}, {%4,%5,%6,%7}, {%8,%9}, {%0,%1,%2,%3};"
        : "+f"(c0), "+f"(c1), "+f"(c2), "+f"(c3)
        : "r"(a0), "r"(a1), "r"(a2), "r"(a3), "r"(b0), "r"(b1));
}
__device__ __forceinline__ uint32_t pack_bf2(__nv_bfloat16 lo, __nv_bfloat16 hi) {
    __nv_bfloat162 v; v.x = lo; v.y = hi;
    return *(uint32_t*)&v;
}

// =============================================================================
// K1 (scalar, measured-good): fc = [f | log_eps] ; QK = fc @ [W_q | W_k]
// =============================================================================
__global__ __launch_bounds__(256) void k1_proj(
    const float* __restrict__ f, const float* __restrict__ le,
    const float* __restrict__ Wq, const float* __restrict__ Wk)
{
    __shared__ float As[32][68];
    __shared__ float Bs[32][132];

    const int t  = threadIdx.x;
    const int ty = t >> 4;
    const int tx = t & 15;
    const int rowBase = blockIdx.x * 64;
    const int b = rowBase / NN;

    float acc[4][8];
    #pragma unroll
    for (int i = 0; i < 4; i++)
        #pragma unroll
        for (int j = 0; j < 8; j++) acc[i][j] = 0.f;

    for (int kc = 0; kc < 9; kc++) {
        const int k0 = kc * 32;
        const int len = (KF - k0 < 32) ? (KF - k0) : 32;
        __syncthreads();
        if (len == 32) {
            #pragma unroll
            for (int it = 0; it < 2; it++) {
                int n  = (t >> 3) + it * 32;
                int kk = (t & 7) * 4;
                float4 v = *(const float4*)&f[(size_t)(rowBase + n) * DF + k0 + kk];
                As[kk + 0][n] = v.x; As[kk + 1][n] = v.y;
                As[kk + 2][n] = v.z; As[kk + 3][n] = v.w;
            }
            #pragma unroll
            for (int it = 0; it < 4; it++) {
                int kk = (t >> 5) + it * 8;
                int h  = (t & 31) * 4;
                int c  = k0 + kk;
                float4 v = (h < 64) ? *(const float4*)&Wq[c * DH + h]
                                    : *(const float4*)&Wk[c * DH + (h - 64)];
                Bs[kk][h + 0] = v.x; Bs[kk][h + 1] = v.y;
                Bs[kk][h + 2] = v.z; Bs[kk][h + 3] = v.w;
            }
        } else {
            float lv = le[b];
            for (int idx = t; idx < 32 * 64; idx += 256) {
                int kk = idx >> 6, n = idx & 63;
                As[kk][n] = (kk == 0) ? lv : 0.f;
            }
            if (t < 32) {
                int h = t * 4;
                float4 v = (h < 64) ? *(const float4*)&Wq[256 * DH + h]
                                    : *(const float4*)&Wk[256 * DH + (h - 64)];
                Bs[0][h + 0] = v.x; Bs[0][h + 1] = v.y;
                Bs[0][h + 2] = v.z; Bs[0][h + 3] = v.w;
            }
        }
        __syncthreads();
        #pragma unroll 8
        for (int kk = 0; kk < 32; kk++) {
            float4 av = *(const float4*)&As[kk][ty * 4];
            float4 b0 = *(const float4*)&Bs[kk][tx * 8];
            float4 b1 = *(const float4*)&Bs[kk][tx * 8 + 4];
            float a[4]  = {av.x, av.y, av.z, av.w};
            float bv[8] = {b0.x, b0.y, b0.z, b0.w, b1.x, b1.y, b1.z, b1.w};
            #pragma unroll
            for (int i = 0; i < 4; i++)
                #pragma unroll
                for (int j = 0; j < 8; j++) acc[i][j] += a[i] * bv[j];
        }
    }
    #pragma unroll
    for (int i = 0; i < 4; i++) {
        int row = rowBase + ty * 4 + i;
        float4 o0 = {acc[i][0], acc[i][1], acc[i][2], acc[i][3]};
        float4 o1 = {acc[i][4], acc[i][5], acc[i][6], acc[i][7]};
        *(float4*)&g_QK[(size_t)row * QKW + tx * 8]     = o0;
        *(float4*)&g_QK[(size_t)row * QKW + tx * 8 + 4] = o1;
    }
}

// =============================================================================
// K2 (bf16 mma.sync, 3-term split): E = exp(q.k/8) -> pi + colsum partials.
// 128n x 128m tile, K=64, **512 threads (16 warps: 4n x 4m)**, warp 32n x 32m.
// Dyn smem bf16: A_hi|A_lo|B_hi|B_lo, each [128][72] (144B rows) = 73728 B.
// 1 CTA/SM (smem), 16 warps -> 4 warps/SMSP latency hiding, no reg cap.
// =============================================================================
#define K2_SMEM_BYTES 73728
#define AB_HI 0
#define AB_LO 18432
#define BB_HI 36864
#define BB_LO 55296
#define S_STR 136
#define CS2F  17408        // float offset of 512-float colsum scratch

__global__ __launch_bounds__(512, 1) void k2_tc(float* __restrict__ pi)
{
    extern __shared__ char sm[];
    float* smf = (float*)sm;
    const int t    = threadIdx.x;
    const int wid  = t >> 5;          // 0..15
    const int lane = t & 31;
    const int g    = lane >> 2;
    const int c4   = lane & 3;
    const int m0   = blockIdx.x * 128;
    const int n0   = blockIdx.y * 128;
    const int b    = blockIdx.z;
    const float* __restrict__ Q = g_QK + (size_t)b * NN * QKW;

    // ---- load + bf16 hi/lo split: 2 threads per row (256 rows: A then B)
    {
        const int rowid = t >> 1;          // 0..255
        const int half  = t & 1;           // 0: gg 0..7, 1: gg 8..15
        const int r     = rowid & 127;
        const bool isA  = rowid < 128;
        const float* src = isA ? &Q[(size_t)(n0 + r) * QKW]
                               : &Q[(size_t)(m0 + r) * QKW + 64];
        char* dhi = sm + (isA ? AB_HI : BB_HI) + r * 144;
        char* dlo = sm + (isA ? AB_LO : BB_LO) + r * 144;
        #pragma unroll
        for (int gi = 0; gi < 8; gi++) {
            int gg = half * 8 + gi;
            float4 v = *(const float4*)&src[gg * 4];
            __nv_bfloat16 hx = __float2bfloat16(v.x);
            __nv_bfloat16 hy = __float2bfloat16(v.y);
            __nv_bfloat16 hz = __float2bfloat16(v.z);
            __nv_bfloat16 hw = __float2bfloat16(v.w);
            __nv_bfloat16 lx = __float2bfloat16(v.x - __bfloat162float(hx));
            __nv_bfloat16 ly = __float2bfloat16(v.y - __bfloat162float(hy));
            __nv_bfloat16 lz = __float2bfloat16(v.z - __bfloat162float(hz));
            __nv_bfloat16 lw = __float2bfloat16(v.w - __bfloat162float(hw));
            *(uint2*)(dhi + gg * 8) = make_uint2(pack_bf2(hx, hy), pack_bf2(hz, hw));
            *(uint2*)(dlo + gg * 8) = make_uint2(pack_bf2(lx, ly), pack_bf2(lz, lw));
        }
    }
    __syncthreads();

    // ---- mainloop: 3 passes x 4 k-steps x 8 mma per warp (32n x 32m tile) ----
    const int warpN = wid >> 2;            // 0..3
    const int warpM = wid & 3;             // 0..3
    const int nbase = warpN * 32;
    const int mbase = warpM * 32;
    const int lane15 = lane & 15;
    const int kby    = (lane >> 4) * 16;

    float acc[2][4][4];                    // [mi(16n)][m-tile(8m)][frag]
    #pragma unroll
    for (int mi = 0; mi < 2; mi++)
        #pragma unroll
        for (int nj = 0; nj < 4; nj++)
            #pragma unroll
            for (int c = 0; c < 4; c++) acc[mi][nj][c] = 0.f;

    #pragma unroll
    for (int p = 0; p < 3; p++) {
        const char* Ab = sm + ((p == 1) ? AB_LO : AB_HI);
        const char* Bb = sm + ((p == 2) ? BB_LO : BB_HI);
        const uint32_t aBase = smem_u32(Ab + (nbase + lane15) * 144 + kby);
        const uint32_t bBase = smem_u32(Bb + (mbase + lane15) * 144 + kby);
        #pragma unroll
        for (int ks = 0; ks < 4; ks++) {
            const uint32_t ko = ks * 32;
            uint32_t a0[4], a1[4];
            ldsm_x4(a0[0], a0[1], a0[2], a0[3], aBase + ko);
            ldsm_x4(a1[0], a1[1], a1[2], a1[3], aBase + 16 * 144 + ko);
            #pragma unroll
            for (int jb = 0; jb < 2; jb++) {
                uint32_t r0, r1, r2, r3;
                ldsm_x4(r0, r1, r2, r3, bBase + jb * 16 * 144 + ko);
                mma_bf16(acc[0][2*jb][0], acc[0][2*jb][1], acc[0][2*jb][2], acc[0][2*jb][3],
                         a0[0], a0[1], a0[2], a0[3], r0, r2);
                mma_bf16(acc[0][2*jb+1][0], acc[0][2*jb+1][1], acc[0][2*jb+1][2], acc[0][2*jb+1][3],
                         a0[0], a0[1], a0[2], a0[3], r1, r3);
                mma_bf16(acc[1][2*jb][0], acc[1][2*jb][1], acc[1][2*jb][2], acc[1][2*jb][3],
                         a1[0], a1[1], a1[2], a1[3], r0, r2);
                mma_bf16(acc[1][2*jb+1][0], acc[1][2*jb+1][1], acc[1][2*jb+1][2], acc[1][2*jb+1][3],
                         a1[0], a1[1], a1[2], a1[3], r1, r3);
            }
        }
    }
    __syncthreads();   // done reading A/B smem; S overlays it

    // ---- exp + stage into S[128][136] ----
    #pragma unroll
    for (int mi = 0; mi < 2; mi++) {
        const int nr0 = nbase + mi * 16 + g;
        #pragma unroll
        for (int nj = 0; nj < 4; nj++) {
            const int mc = mbase + nj * 8 + 2 * c4;
            float e0 = __expf(acc[mi][nj][0] * 0.125f);
            float e1 = __expf(acc[mi][nj][1] * 0.125f);
            float e2 = __expf(acc[mi][nj][2] * 0.125f);
            float e3 = __expf(acc[mi][nj][3] * 0.125f);
            *(float2*)&smf[nr0 * S_STR + mc]       = make_float2(e0, e1);
            *(float2*)&smf[(nr0 + 8) * S_STR + mc] = make_float2(e2, e3);
        }
    }
    __syncthreads();

    // ---- coalesced pi stores from S (16 warps x 8 rows) ----
    const size_t piBase = (size_t)b * NN * NN;
    #pragma unroll
    for (int i = 0; i < 8; i++) {
        int row = wid + i * 16;
        float4 v = *(const float4*)&smf[row * S_STR + lane * 4];
        *(float4*)&pi[piBase + (size_t)(n0 + row) * NN + m0 + lane * 4] = v;
    }

    // ---- deterministic column sums (4 threads per column, 32 rows each) ----
    {
        const int col = t & 127, q = t >> 7;    // q = 0..3
        float s = 0.f;
        #pragma unroll 8
        for (int n = 0; n < 32; n++) s += smf[(q * 32 + n) * S_STR + col];
        smf[CS2F + q * 128 + col] = s;
    }
    __syncthreads();
    if (t < 128) {
        float s = smf[CS2F + t] + smf[CS2F + 128 + t]
                + smf[CS2F + 256 + t] + smf[CS2F + 384 + t];
        g_cs_part[(size_t)(b * 16 + blockIdx.y) * NN + m0 + t] = s;
    }
}

// K2b: colsum[b][m] = sum over 16 n-tiles
__global__ void k2b_reduce()
{
    int i = blockIdx.x * 256 + threadIdx.x;
    int b = i >> 11, m = i & (NN - 1);
    float s = 0.f;
    #pragma unroll
    for (int nt = 0; nt < 16; nt++) s += g_cs_part[(size_t)(b * 16 + nt) * NN + m];
    g_cs[i] = s;
}

// =============================================================================
// K3 (R10 measured-good): normalize pi in place + y partials
// =============================================================================
__global__ __launch_bounds__(256) void k3_norm(
    const float* __restrict__ x, float* __restrict__ pi)
{
    __shared__ float xs[128 * 3];
    const int t  = threadIdx.x;
    const int m  = blockIdx.x * 256 + t;
    const int nc = blockIdx.y;
    const int b  = blockIdx.z;
    const float* xb = x + (size_t)b * NN * 3 + (size_t)(nc * 128) * 3;
    for (int i = t; i < 128 * 3; i += 256) xs[i] = xb[i];
    const float inv  = 1.0f / g_cs[(size_t)b * NN + m];
    const float invN = 1.0f / (float)NN;
    __syncthreads();

    float a0 = 0.f, a1 = 0.f, a2 = 0.f;
    size_t base = (size_t)b * NN * NN + (size_t)(nc * 128) * NN + m;
    #pragma unroll 2
    for (int nb = 0; nb < 16; nb++) {
        float* pp = pi + base + (size_t)(nb * 8) * NN;
        float e[8];
        #pragma unroll
        for (int u = 0; u < 8; u++) e[u] = __ldcs(pp + (size_t)u * NN);
        #pragma unroll
        for (int u = 0; u < 8; u++) {
            float p = e[u] * inv;
            __stcs(pp + (size_t)u * NN, p * invN);
            int n = nb * 8 + u;
            a0 += p * xs[n * 3 + 0];
            a1 += p * xs[n * 3 + 1];
            a2 += p * xs[n * 3 + 2];
        }
    }
    size_t yi = ((size_t)(b * 16 + nc) * NN + m) * 3;
    g_y_part[yi + 0] = a0;
    g_y_part[yi + 1] = a1;
    g_y_part[yi + 2] = a2;
}

// K4: reduce y partials into d_out's y region
__global__ void k4_reduce(float* __restrict__ y)
{
    int i = blockIdx.x * 256 + threadIdx.x;
    int b = i / (NN * 3);
    int r = i - b * (NN * 3);
    float s = 0.f;
    #pragma unroll
    for (int nc = 0; nc < 16; nc++)
        s += g_y_part[(size_t)(b * 16 + nc) * (NN * 3) + r];
    y[i] = s;
}

// =============================================================================
extern "C" void kernel_launch(void* const* d_in, const int* in_sizes, int n_in,
                              void* d_out, int out_size)
{
    const float* f  = (const float*)d_in[0];   // (B, N, 256)
    const float* x  = (const float*)d_in[1];   // (B, N, 3)
    const float* le = (const float*)d_in[2];   // (B,)
    const float* Wq = (const float*)d_in[3];   // (257, 64)
    const float* Wk = (const float*)d_in[4];   // (257, 64)

    float* out = (float*)d_out;
    float* y   = out;                          // (B, N, 3)
    float* pi  = out + (size_t)BB * NN * 3;    // (B, N, N)

    static int smem_set = 0;
    if (!smem_set) {
        cudaFuncSetAttribute(k2_tc, cudaFuncAttributeMaxDynamicSharedMemorySize,
                             K2_SMEM_BYTES);
        smem_set = 1;
    }

    k1_proj<<<(BB * NN) / 64, 256>>>(f, le, Wq, Wk);
    k2_tc<<<dim3(16, 16, BB), 512, K2_SMEM_BYTES>>>(pi);
    k2b_reduce<<<(BB * NN) / 256, 256>>>();
    k3_norm<<<dim3(8, 16, BB), 256>>>(x, pi);
    k4_reduce<<<(BB * NN * 3) / 256, 256>>>(y);
}